// round 8
// baseline (speedup 1.0000x reference)
#include <cuda_runtime.h>
#include <math.h>

// FFT long conv, N = 16384 = 4^7, one CTA per row.
// R8: __sincosf (MUFU-throughput bottleneck, ~24.5K cyc/row) replaced by SMEM
// twiddle tables (2184 float2, built once per launch by a tiny init kernel in
// double precision, copied to SMEM per CTA). Per butterfly: 2 conflict-free
// LDS.64 twiddle loads + 4-cmul power chain.

#define L_SIG  8192
#define N_FFT  16384
#define NT     512
#define SMEM_F2    (N_FFT + (N_FFT >> 4))          // 17408 float2 for data
#define TW_ENTRIES 2184
#define SMEM_TOTAL_F2 (SMEM_F2 + TW_ENTRIES)       // 19592 float2
#define SMEM_BYTES (SMEM_TOTAL_F2 * 8)             // 156736 B

__device__ __align__(16) float2 g_twiddle[TW_ENTRIES];

__device__ __forceinline__ int SKEW(int i) { return i + (i >> 4); }

__device__ __forceinline__ float2 cadd(float2 a, float2 b) { return make_float2(a.x + b.x, a.y + b.y); }
__device__ __forceinline__ float2 csub(float2 a, float2 b) { return make_float2(a.x - b.x, a.y - b.y); }
__device__ __forceinline__ float2 cmul(float2 a, float2 b) {
    return make_float2(fmaf(a.x, b.x, -a.y * b.y), fmaf(a.x, b.y, a.y * b.x));
}
__device__ __forceinline__ float2 cconj(float2 a) { return make_float2(a.x, -a.y); }

// reverse six base-4 digits of a 12-bit value
__device__ __forceinline__ int rev6_base4(int c) {
    unsigned r = __brev((unsigned)c) >> 20;
    return (int)(((r & 0xAAAu) >> 1) | ((r & 0x555u) << 1));
}

__device__ __forceinline__ void dft4_fwd(float2& a0, float2& a1, float2& a2, float2& a3) {
    float2 t0 = cadd(a0, a2), t1 = csub(a0, a2), t2 = cadd(a1, a3), t3 = csub(a1, a3);
    a0 = cadd(t0, t2); a2 = csub(t0, t2);
    a1 = make_float2(t1.x + t3.y, t1.y - t3.x);   // t1 - i*t3
    a3 = make_float2(t1.x - t3.y, t1.y + t3.x);   // t1 + i*t3
}
__device__ __forceinline__ void dft4_inv(float2& a0, float2& a1, float2& a2, float2& a3) {
    float2 t0 = cadd(a0, a2), t1 = csub(a0, a2), t2 = cadd(a1, a3), t3 = csub(a1, a3);
    a0 = cadd(t0, t2); a2 = csub(t0, t2);
    a1 = make_float2(t1.x - t3.y, t1.y + t3.x);   // t1 + i*t3
    a3 = make_float2(t1.x + t3.y, t1.y - t3.x);   // t1 - i*t3
}

// omega16^k = e^{-+ 2*pi*i*k/16}; k compile-time after unroll (k in {0..9})
__device__ __forceinline__ float2 om16(int k, bool inv) {
    const float OC[10] = {1.f, 0.9238795325f, 0.7071067812f, 0.3826834324f, 0.f,
                          0.f, -0.7071067812f, 0.f, 0.f, -0.9238795325f};
    const float OS[10] = {0.f, 0.3826834324f, 0.7071067812f, 0.9238795325f, 1.f,
                          0.f, 0.7071067812f, 0.f, 0.f, -0.3826834324f};
    return make_float2(OC[k], inv ? OS[k] : -OS[k]);
}

// Twiddle table layout (float2 units from table base):
//   [0,1024)    : e^{-2pi i j/16384}  (S=1024, W)
//   [1024,2048) : e^{-2pi i j/4096}   (S=1024, W^4)
//   [2048,2112) : e^{-2pi i j/1024}   (S=64,   W)
//   [2112,2176) : e^{-2pi i j/256}    (S=64,   W^4)
//   [2176,2180) : e^{-2pi i j/64}     (S=4,    W)
//   [2180,2184) : e^{-2pi i j/16}     (S=4,    W^4)
__global__ void twinit_kernel() {
    for (int i = threadIdx.x; i < TW_ENTRIES; i += blockDim.x) {
        int j; double denom;
        if      (i < 1024) { j = i;        denom = 16384.0; }
        else if (i < 2048) { j = i - 1024; denom = 4096.0; }
        else if (i < 2112) { j = i - 2048; denom = 1024.0; }
        else if (i < 2176) { j = i - 2112; denom = 256.0; }
        else if (i < 2180) { j = i - 2176; denom = 64.0; }
        else               { j = i - 2180; denom = 16.0; }
        double a = -6.283185307179586476925286766559 * (double)j / denom;
        g_twiddle[i] = make_float2((float)cos(a), (float)sin(a));
    }
}

// Radix-16 pass at stride S: fwd DIF levels (m=4S) then (m=S); inv DIT reversed.
// Twiddle bases W, W^4 from SMEM table; powers W2,W3,W8,W12 via 4 cmuls.
template<int S, int T1, int T4, bool INV>
__device__ __forceinline__ void radix16_pass(float2* z, const float2* tw, int tid) {
    #pragma unroll
    for (int it = 0; it < (N_FFT / 16) / NT; it++) {
        const int idx = tid + it * NT;
        const int j = idx & (S - 1);
        const int base = (idx / S) * (16 * S) + j;

        float2 b[16];
        #pragma unroll
        for (int r = 0; r < 16; r++) b[r] = z[SKEW(base + S * r)];

        float2 W  = tw[T1 + j];
        float2 W4 = tw[T4 + j];
        if (INV) { W.y = -W.y; W4.y = -W4.y; }
        const float2 W2  = cmul(W, W);
        const float2 W3  = cmul(W2, W);
        const float2 W8  = cmul(W4, W4);
        const float2 W12 = cmul(W8, W4);

        if (!INV) {
            #pragma unroll
            for (int r0 = 0; r0 < 4; r0++) {     // level m = 4S
                float2 a0 = b[r0], a1 = b[r0 + 4], a2 = b[r0 + 8], a3 = b[r0 + 12];
                dft4_fwd(a0, a1, a2, a3);
                b[r0]      = a0;
                b[r0 + 4]  = cmul(a1, r0 ? cmul(W,  om16(r0,     false)) : W);
                b[r0 + 8]  = cmul(a2, r0 ? cmul(W2, om16(2 * r0, false)) : W2);
                b[r0 + 12] = cmul(a3, r0 ? cmul(W3, om16(3 * r0, false)) : W3);
            }
            #pragma unroll
            for (int d = 0; d < 4; d++) {        // level m = S
                float2 a0 = b[4*d], a1 = b[4*d+1], a2 = b[4*d+2], a3 = b[4*d+3];
                dft4_fwd(a0, a1, a2, a3);
                b[4*d]   = a0;
                b[4*d+1] = cmul(a1, W4);
                b[4*d+2] = cmul(a2, W8);
                b[4*d+3] = cmul(a3, W12);
            }
        } else {
            #pragma unroll
            for (int d = 0; d < 4; d++) {        // level m = S
                float2 a0 = b[4*d];
                float2 a1 = cmul(b[4*d+1], W4);
                float2 a2 = cmul(b[4*d+2], W8);
                float2 a3 = cmul(b[4*d+3], W12);
                dft4_inv(a0, a1, a2, a3);
                b[4*d] = a0; b[4*d+1] = a1; b[4*d+2] = a2; b[4*d+3] = a3;
            }
            #pragma unroll
            for (int r0 = 0; r0 < 4; r0++) {     // level m = 4S
                float2 a0 = b[r0];
                float2 a1 = cmul(b[r0 + 4],  r0 ? cmul(W,  om16(r0,     true)) : W);
                float2 a2 = cmul(b[r0 + 8],  r0 ? cmul(W2, om16(2 * r0, true)) : W2);
                float2 a3 = cmul(b[r0 + 12], r0 ? cmul(W3, om16(3 * r0, true)) : W3);
                dft4_inv(a0, a1, a2, a3);
                b[r0] = a0; b[r0 + 4] = a1; b[r0 + 8] = a2; b[r0 + 12] = a3;
            }
        }

        #pragma unroll
        for (int r = 0; r < 16; r++) z[SKEW(base + S * r)] = b[r];
    }
}

// Fused: fwd radix-4 (m=1) + spectral combine + inv radix-4 (m=1). Twiddle-free.
__device__ __forceinline__ void fused_mid(float2* z, int tid) {
    for (int c = tid; c < N_FFT / 4; c += NT) {
        if (c == 0) {
            float2 A0 = z[SKEW(0)], A1 = z[SKEW(1)], A2 = z[SKEW(2)], A3 = z[SKEW(3)];
            dft4_fwd(A0, A1, A2, A3);            // freqs 0, 4096, 8192, 12288
            float2 Y0 = make_float2(A0.x * A0.y, 0.0f);       // DC: both real
            float2 Y2 = make_float2(A2.x * A2.y, 0.0f);       // Nyquist: both real
            float2 Za = A1, Zb = A3;                           // 4096 <-> 12288
            float2 X = make_float2(0.5f * (Za.x + Zb.x), 0.5f * (Za.y - Zb.y));
            float2 H = make_float2(0.5f * (Za.y + Zb.y), 0.5f * (Zb.x - Za.x));
            float2 Y1 = cmul(X, H);
            float2 Y3 = cconj(Y1);
            dft4_inv(Y0, Y1, Y2, Y3);
            z[SKEW(0)] = Y0; z[SKEW(1)] = Y1; z[SKEW(2)] = Y2; z[SKEW(3)] = Y3;
            continue;
        }
        const int k0 = rev6_base4(c);
        const int cp = rev6_base4(4096 - k0);
        if (c > cp) continue;                    // partner thread handles it (c==cp: self)

        float2 A[4], B[4];
        #pragma unroll
        for (int t = 0; t < 4; t++) A[t] = z[SKEW(4 * c + t)];
        #pragma unroll
        for (int t = 0; t < 4; t++) B[t] = z[SKEW(4 * cp + t)];

        dft4_fwd(A[0], A[1], A[2], A[3]);
        dft4_fwd(B[0], B[1], B[2], B[3]);

        float2 An[4], Bn[4];
        #pragma unroll
        for (int t = 0; t < 4; t++) {
            float2 Za = A[t], Zb = B[3 - t];
            float2 X = make_float2(0.5f * (Za.x + Zb.x), 0.5f * (Za.y - Zb.y));
            float2 H = make_float2(0.5f * (Za.y + Zb.y), 0.5f * (Zb.x - Za.x));
            float2 Y = cmul(X, H);
            An[t] = Y;
            Bn[3 - t] = cconj(Y);
        }

        dft4_inv(An[0], An[1], An[2], An[3]);
        dft4_inv(Bn[0], Bn[1], Bn[2], Bn[3]);

        #pragma unroll
        for (int t = 0; t < 4; t++) z[SKEW(4 * c + t)] = An[t];
        #pragma unroll
        for (int t = 0; t < 4; t++) z[SKEW(4 * cp + t)] = Bn[t];
    }
}

__global__ __launch_bounds__(NT, 1)
void fftconv_kernel(const float* __restrict__ x, const float* __restrict__ h,
                    float* __restrict__ y) {
    extern __shared__ float2 z[];
    float2* tw = z + SMEM_F2;                    // twiddle tables after data
    const int row = blockIdx.x;
    const int tid = threadIdx.x;

    // copy twiddle table (2184 float2 = 1092 float4) from global to SMEM
    {
        const float4* gt = (const float4*)g_twiddle;
        float4* st = (float4*)tw;
        #pragma unroll
        for (int j = tid; j < TW_ENTRIES / 2; j += NT) st[j] = gt[j];
    }

    const float4* x4 = (const float4*)(x + (size_t)row * L_SIG);
    const float4* h4 = (const float4*)(h + (size_t)row * L_SIG);

    #pragma unroll
    for (int j = tid; j < L_SIG / 4; j += NT) {
        float4 xv = x4[j], hv = h4[j];
        z[SKEW(4 * j + 0)] = make_float2(xv.x, hv.x);
        z[SKEW(4 * j + 1)] = make_float2(xv.y, hv.y);
        z[SKEW(4 * j + 2)] = make_float2(xv.z, hv.z);
        z[SKEW(4 * j + 3)] = make_float2(xv.w, hv.w);
    }
    #pragma unroll
    for (int j = tid; j < L_SIG; j += NT)
        z[SKEW(L_SIG + j)] = make_float2(0.0f, 0.0f);
    __syncthreads();

    radix16_pass<1024,    0, 1024, false>(z, tw, tid); __syncthreads();
    radix16_pass<64,   2048, 2112, false>(z, tw, tid); __syncthreads();
    radix16_pass<4,    2176, 2180, false>(z, tw, tid); __syncthreads();
    fused_mid(z, tid);                                 __syncthreads();
    radix16_pass<4,    2176, 2180, true >(z, tw, tid); __syncthreads();
    radix16_pass<64,   2048, 2112, true >(z, tw, tid); __syncthreads();
    radix16_pass<1024,    0, 1024, true >(z, tw, tid); __syncthreads();

    const float scale = 1.0f / ((float)N_FFT * (float)N_FFT);
    float4* y4 = (float4*)(y + (size_t)row * L_SIG);
    #pragma unroll
    for (int j = tid; j < L_SIG / 4; j += NT) {
        float2 v0 = z[SKEW(4 * j + 0)];
        float2 v1 = z[SKEW(4 * j + 1)];
        float2 v2 = z[SKEW(4 * j + 2)];
        float2 v3 = z[SKEW(4 * j + 3)];
        y4[j] = make_float4(v0.x * scale, v1.x * scale, v2.x * scale, v3.x * scale);
    }
}

extern "C" void kernel_launch(void* const* d_in, const int* in_sizes, int n_in,
                              void* d_out, int out_size) {
    const float* x = (const float*)d_in[0];
    const float* h = (const float*)d_in[1];
    float* y = (float*)d_out;

    cudaFuncSetAttribute(fftconv_kernel,
                         cudaFuncAttributeMaxDynamicSharedMemorySize, SMEM_BYTES);

    twinit_kernel<<<1, 256>>>();
    const int B = in_sizes[0] / L_SIG;   // 4096 rows
    fftconv_kernel<<<B, NT, SMEM_BYTES>>>(x, h, y);
}

// round 9
// speedup vs baseline: 1.1951x; 1.1951x over previous
#include <cuda_runtime.h>

// FFT long conv, N = 16384 = 4^7, one CTA per row. R9:
//  - pass 1 (fwd S=1024) fused with global load; exploits zero-padded upper half
//    (a2=a3=0 in level-1 dft4s) -> no initial SMEM fill, no zero-fill, -1 barrier.
//  - pass 7 (inv S=1024) fused with global store; computes only Re(outputs 0..8191)
//    and writes them scaled, coalesced -> no final STS / output loop, -1 barrier.
//  - middle passes: register radix-16, skewed conflict-free SMEM, __sincosf twiddles.

#define L_SIG  8192
#define N_FFT  16384
#define NT     512
#define SMEM_F2 (N_FFT + (N_FFT >> 4))     // 17408 float2
#define SMEM_BYTES (SMEM_F2 * 8)           // 139264 B

__device__ __forceinline__ int SKEW(int i) { return i + (i >> 4); }

__device__ __forceinline__ float2 cadd(float2 a, float2 b) { return make_float2(a.x + b.x, a.y + b.y); }
__device__ __forceinline__ float2 csub(float2 a, float2 b) { return make_float2(a.x - b.x, a.y - b.y); }
__device__ __forceinline__ float2 cmul(float2 a, float2 b) {
    return make_float2(fmaf(a.x, b.x, -a.y * b.y), fmaf(a.x, b.y, a.y * b.x));
}
__device__ __forceinline__ float2 cconj(float2 a) { return make_float2(a.x, -a.y); }

// reverse six base-4 digits of a 12-bit value
__device__ __forceinline__ int rev6_base4(int c) {
    unsigned r = __brev((unsigned)c) >> 20;
    return (int)(((r & 0xAAAu) >> 1) | ((r & 0x555u) << 1));
}

__device__ __forceinline__ void dft4_fwd(float2& a0, float2& a1, float2& a2, float2& a3) {
    float2 t0 = cadd(a0, a2), t1 = csub(a0, a2), t2 = cadd(a1, a3), t3 = csub(a1, a3);
    a0 = cadd(t0, t2); a2 = csub(t0, t2);
    a1 = make_float2(t1.x + t3.y, t1.y - t3.x);   // t1 - i*t3
    a3 = make_float2(t1.x - t3.y, t1.y + t3.x);   // t1 + i*t3
}
__device__ __forceinline__ void dft4_inv(float2& a0, float2& a1, float2& a2, float2& a3) {
    float2 t0 = cadd(a0, a2), t1 = csub(a0, a2), t2 = cadd(a1, a3), t3 = csub(a1, a3);
    a0 = cadd(t0, t2); a2 = csub(t0, t2);
    a1 = make_float2(t1.x - t3.y, t1.y + t3.x);   // t1 + i*t3
    a3 = make_float2(t1.x + t3.y, t1.y - t3.x);   // t1 - i*t3
}

// omega16^k = e^{-+ 2*pi*i*k/16}; k compile-time after unroll (k in {0..9})
__device__ __forceinline__ float2 om16(int k, bool inv) {
    const float OC[10] = {1.f, 0.9238795325f, 0.7071067812f, 0.3826834324f, 0.f,
                          0.f, -0.7071067812f, 0.f, 0.f, -0.9238795325f};
    const float OS[10] = {0.f, 0.3826834324f, 0.7071067812f, 0.9238795325f, 1.f,
                          0.f, 0.7071067812f, 0.f, 0.f, -0.3826834324f};
    return make_float2(OC[k], inv ? OS[k] : -OS[k]);
}

// ---- fused forward pass, S=1024, reads x,h from gmem (upper half implicit zero) ----
__device__ __forceinline__ void pass1_fused(float2* z, const float* __restrict__ xr,
                                            const float* __restrict__ hr, int tid) {
    const float tstep = -6.2831853071795864f / 16384.0f;
    #pragma unroll
    for (int it = 0; it < 2; it++) {
        const int j = tid + it * NT;

        float2 in[8];
        #pragma unroll
        for (int r = 0; r < 8; r++)
            in[r] = make_float2(xr[j + 1024 * r], hr[j + 1024 * r]);

        float sn, cs;
        __sincosf(tstep * (float)j, &sn, &cs);
        const float2 W   = make_float2(cs, sn);
        const float2 W2  = cmul(W, W);
        const float2 W3  = cmul(W2, W);
        const float2 W4  = cmul(W2, W2);
        const float2 W8  = cmul(W4, W4);
        const float2 W12 = cmul(W8, W4);

        float2 b[16];
        #pragma unroll
        for (int r0 = 0; r0 < 4; r0++) {         // level m = 4096, a2=a3=0
            float2 a0 = in[r0], a1 = in[r0 + 4];
            float2 y0 = cadd(a0, a1);
            float2 y2 = csub(a0, a1);
            float2 y1 = make_float2(a0.x + a1.y, a0.y - a1.x);  // a0 - i*a1
            float2 y3 = make_float2(a0.x - a1.y, a0.y + a1.x);  // a0 + i*a1
            b[r0]      = y0;
            b[r0 + 4]  = cmul(y1, r0 ? cmul(W,  om16(r0,     false)) : W);
            b[r0 + 8]  = cmul(y2, r0 ? cmul(W2, om16(2 * r0, false)) : W2);
            b[r0 + 12] = cmul(y3, r0 ? cmul(W3, om16(3 * r0, false)) : W3);
        }
        #pragma unroll
        for (int d = 0; d < 4; d++) {            // level m = 1024
            float2 a0 = b[4*d], a1 = b[4*d+1], a2 = b[4*d+2], a3 = b[4*d+3];
            dft4_fwd(a0, a1, a2, a3);
            b[4*d]   = a0;
            b[4*d+1] = cmul(a1, W4);
            b[4*d+2] = cmul(a2, W8);
            b[4*d+3] = cmul(a3, W12);
        }
        #pragma unroll
        for (int r = 0; r < 16; r++) z[SKEW(j + 1024 * r)] = b[r];
    }
}

// ---- fused inverse pass, S=1024, writes Re(outputs 0..8191)*scale to gmem ----
__device__ __forceinline__ void pass7_fused(const float2* z, float* __restrict__ yr, int tid) {
    const float tstep = 6.2831853071795864f / 16384.0f;
    const float scale = 1.0f / (16384.0f * 16384.0f);
    #pragma unroll
    for (int it = 0; it < 2; it++) {
        const int j = tid + it * NT;

        float2 b[16];
        #pragma unroll
        for (int r = 0; r < 16; r++) b[r] = z[SKEW(j + 1024 * r)];

        float sn, cs;
        __sincosf(tstep * (float)j, &sn, &cs);
        const float2 W   = make_float2(cs, sn);
        const float2 W2  = cmul(W, W);
        const float2 W3  = cmul(W2, W);
        const float2 W4  = cmul(W2, W2);
        const float2 W8  = cmul(W4, W4);
        const float2 W12 = cmul(W8, W4);

        #pragma unroll
        for (int d = 0; d < 4; d++) {            // level m = 1024 (full complex)
            float2 a0 = b[4*d];
            float2 a1 = cmul(b[4*d+1], W4);
            float2 a2 = cmul(b[4*d+2], W8);
            float2 a3 = cmul(b[4*d+3], W12);
            dft4_inv(a0, a1, a2, a3);
            b[4*d] = a0; b[4*d+1] = a1; b[4*d+2] = a2; b[4*d+3] = a3;
        }
        #pragma unroll
        for (int r0 = 0; r0 < 4; r0++) {         // level m = 4096: Re of outs 0..7 only
            float2 in0 = b[r0];
            float2 in1 = cmul(b[r0 + 4],  r0 ? cmul(W,  om16(r0,     true)) : W);
            float  in2x;
            {
                float2 w = r0 ? cmul(W2, om16(2 * r0, true)) : W2;
                float2 v = b[r0 + 8];
                in2x = fmaf(v.x, w.x, -v.y * w.y);      // Re(v * w)
            }
            float2 in3 = cmul(b[r0 + 12], r0 ? cmul(W3, om16(3 * r0, true)) : W3);
            float re0 = (in0.x + in2x) + (in1.x + in3.x);   // Re(out[r0])
            float re1 = (in0.x - in2x) - (in1.y - in3.y);   // Re(out[r0+4])
            yr[j + 1024 * r0]       = re0 * scale;
            yr[j + 1024 * (r0 + 4)] = re1 * scale;
        }
    }
}

// ---- generic radix-16 pass (middle passes: S=64, S=4), sincosf twiddles ----
template<int S, bool INV>
__device__ __forceinline__ void radix16_pass(float2* z, int tid) {
    const float ang0 = (INV ? 6.2831853071795864f : -6.2831853071795864f) / (16.0f * (float)S);
    #pragma unroll
    for (int it = 0; it < (N_FFT / 16) / NT; it++) {
        const int idx = tid + it * NT;
        const int j = idx & (S - 1);
        const int base = (idx / S) * (16 * S) + j;

        float2 b[16];
        #pragma unroll
        for (int r = 0; r < 16; r++) b[r] = z[SKEW(base + S * r)];

        float sn, cs;
        __sincosf(ang0 * (float)j, &sn, &cs);
        const float2 W   = make_float2(cs, sn);
        const float2 W2  = cmul(W, W);
        const float2 W3  = cmul(W2, W);
        const float2 W4  = cmul(W2, W2);
        const float2 W8  = cmul(W4, W4);
        const float2 W12 = cmul(W8, W4);

        if (!INV) {
            #pragma unroll
            for (int r0 = 0; r0 < 4; r0++) {     // level m = 4S
                float2 a0 = b[r0], a1 = b[r0 + 4], a2 = b[r0 + 8], a3 = b[r0 + 12];
                dft4_fwd(a0, a1, a2, a3);
                b[r0]      = a0;
                b[r0 + 4]  = cmul(a1, r0 ? cmul(W,  om16(r0,     false)) : W);
                b[r0 + 8]  = cmul(a2, r0 ? cmul(W2, om16(2 * r0, false)) : W2);
                b[r0 + 12] = cmul(a3, r0 ? cmul(W3, om16(3 * r0, false)) : W3);
            }
            #pragma unroll
            for (int d = 0; d < 4; d++) {        // level m = S
                float2 a0 = b[4*d], a1 = b[4*d+1], a2 = b[4*d+2], a3 = b[4*d+3];
                dft4_fwd(a0, a1, a2, a3);
                b[4*d]   = a0;
                b[4*d+1] = cmul(a1, W4);
                b[4*d+2] = cmul(a2, W8);
                b[4*d+3] = cmul(a3, W12);
            }
        } else {
            #pragma unroll
            for (int d = 0; d < 4; d++) {        // level m = S
                float2 a0 = b[4*d];
                float2 a1 = cmul(b[4*d+1], W4);
                float2 a2 = cmul(b[4*d+2], W8);
                float2 a3 = cmul(b[4*d+3], W12);
                dft4_inv(a0, a1, a2, a3);
                b[4*d] = a0; b[4*d+1] = a1; b[4*d+2] = a2; b[4*d+3] = a3;
            }
            #pragma unroll
            for (int r0 = 0; r0 < 4; r0++) {     // level m = 4S
                float2 a0 = b[r0];
                float2 a1 = cmul(b[r0 + 4],  r0 ? cmul(W,  om16(r0,     true)) : W);
                float2 a2 = cmul(b[r0 + 8],  r0 ? cmul(W2, om16(2 * r0, true)) : W2);
                float2 a3 = cmul(b[r0 + 12], r0 ? cmul(W3, om16(3 * r0, true)) : W3);
                dft4_inv(a0, a1, a2, a3);
                b[r0] = a0; b[r0 + 4] = a1; b[r0 + 8] = a2; b[r0 + 12] = a3;
            }
        }

        #pragma unroll
        for (int r = 0; r < 16; r++) z[SKEW(base + S * r)] = b[r];
    }
}

// Fused: fwd radix-4 (m=1) + spectral combine + inv radix-4 (m=1). Twiddle-free.
__device__ __forceinline__ void fused_mid(float2* z, int tid) {
    for (int c = tid; c < N_FFT / 4; c += NT) {
        if (c == 0) {
            float2 A0 = z[SKEW(0)], A1 = z[SKEW(1)], A2 = z[SKEW(2)], A3 = z[SKEW(3)];
            dft4_fwd(A0, A1, A2, A3);            // freqs 0, 4096, 8192, 12288
            float2 Y0 = make_float2(A0.x * A0.y, 0.0f);       // DC: both real
            float2 Y2 = make_float2(A2.x * A2.y, 0.0f);       // Nyquist: both real
            float2 Za = A1, Zb = A3;                           // 4096 <-> 12288
            float2 X = make_float2(0.5f * (Za.x + Zb.x), 0.5f * (Za.y - Zb.y));
            float2 H = make_float2(0.5f * (Za.y + Zb.y), 0.5f * (Zb.x - Za.x));
            float2 Y1 = cmul(X, H);
            float2 Y3 = cconj(Y1);
            dft4_inv(Y0, Y1, Y2, Y3);
            z[SKEW(0)] = Y0; z[SKEW(1)] = Y1; z[SKEW(2)] = Y2; z[SKEW(3)] = Y3;
            continue;
        }
        const int k0 = rev6_base4(c);
        const int cp = rev6_base4(4096 - k0);
        if (c > cp) continue;                    // partner thread handles it (c==cp: self)

        float2 A[4], B[4];
        #pragma unroll
        for (int t = 0; t < 4; t++) A[t] = z[SKEW(4 * c + t)];
        #pragma unroll
        for (int t = 0; t < 4; t++) B[t] = z[SKEW(4 * cp + t)];

        dft4_fwd(A[0], A[1], A[2], A[3]);
        dft4_fwd(B[0], B[1], B[2], B[3]);

        float2 An[4], Bn[4];
        #pragma unroll
        for (int t = 0; t < 4; t++) {
            float2 Za = A[t], Zb = B[3 - t];
            float2 X = make_float2(0.5f * (Za.x + Zb.x), 0.5f * (Za.y - Zb.y));
            float2 H = make_float2(0.5f * (Za.y + Zb.y), 0.5f * (Zb.x - Za.x));
            float2 Y = cmul(X, H);
            An[t] = Y;
            Bn[3 - t] = cconj(Y);
        }

        dft4_inv(An[0], An[1], An[2], An[3]);
        dft4_inv(Bn[0], Bn[1], Bn[2], Bn[3]);

        #pragma unroll
        for (int t = 0; t < 4; t++) z[SKEW(4 * c + t)] = An[t];
        #pragma unroll
        for (int t = 0; t < 4; t++) z[SKEW(4 * cp + t)] = Bn[t];
    }
}

__global__ __launch_bounds__(NT, 1)
void fftconv_kernel(const float* __restrict__ x, const float* __restrict__ h,
                    float* __restrict__ y) {
    extern __shared__ float2 z[];
    const int row = blockIdx.x;
    const int tid = threadIdx.x;
    const float* xr = x + (size_t)row * L_SIG;
    const float* hr = h + (size_t)row * L_SIG;
    float* yr = y + (size_t)row * L_SIG;

    pass1_fused(z, xr, hr, tid);       __syncthreads();
    radix16_pass<64, false>(z, tid);   __syncthreads();
    radix16_pass<4,  false>(z, tid);   __syncthreads();
    fused_mid(z, tid);                 __syncthreads();
    radix16_pass<4,  true >(z, tid);   __syncthreads();
    radix16_pass<64, true >(z, tid);   __syncthreads();
    pass7_fused(z, yr, tid);
}

extern "C" void kernel_launch(void* const* d_in, const int* in_sizes, int n_in,
                              void* d_out, int out_size) {
    const float* x = (const float*)d_in[0];
    const float* h = (const float*)d_in[1];
    float* y = (float*)d_out;

    cudaFuncSetAttribute(fftconv_kernel,
                         cudaFuncAttributeMaxDynamicSharedMemorySize, SMEM_BYTES);

    const int B = in_sizes[0] / L_SIG;   // 4096 rows
    fftconv_kernel<<<B, NT, SMEM_BYTES>>>(x, h, y);
}